// round 11
// baseline (speedup 1.0000x reference)
#include <cuda_runtime.h>
#include <cuda_bf16.h>
#include <cstdint>

// Problem: x [4096, 4096] fp32, A/B [4, 512, 512] fp32 -> out [4096, 16384] fp32
#define G_DIM 4
#define K_BLK 8
#define H_DIM 512
#define N_COLS 2048            // G*H: GEMM output columns (n = g*512 + p)
#define BSZ 4096
#define M_MAIN 32768           // BSZ * K_BLK
#define KDIM 512

// GEMM tiling (mma.sync path, base ISA only — no 'a' features)
#define BM 128
#define BN 128
#define BK 32                  // K elems per stage chunk (64 B bf16 rows)
#define KSTEPS (KDIM / BK)     // 16
#define NTHREADS 256
#define NSTAGES 4
#define TILE_B 8192            // 128 rows x 64 B
#define STAGE_B (4 * TILE_B)   // Ahi, Alo, Bhi, Blo = 32 KB
#define SMEM_REQ (NSTAGES * STAGE_B)   // 131072

// ---------------------------------------------------------------------------
// Static device scratch (no runtime allocation allowed)
// ---------------------------------------------------------------------------
__device__ __nv_bfloat16 g_Xhi[(size_t)M_MAIN * KDIM];
__device__ __nv_bfloat16 g_Xlo[(size_t)M_MAIN * KDIM];
__device__ __nv_bfloat16 g_Whi[(size_t)N_COLS * KDIM];   // (A-B)
__device__ __nv_bfloat16 g_Wlo[(size_t)N_COLS * KDIM];
__device__ __nv_bfloat16 g_Bhi[(size_t)N_COLS * KDIM];   // B
__device__ __nv_bfloat16 g_Blo[(size_t)N_COLS * KDIM];
__device__ __nv_bfloat16 g_Shi[(size_t)BSZ * KDIM];      // sum_k x3
__device__ __nv_bfloat16 g_Slo[(size_t)BSZ * KDIM];
__device__ float         g_T  [(size_t)BSZ * N_COLS];    // T = S @ B^T

// ---------------------------------------------------------------------------
// Base-ISA PTX helpers (sm_80-class: cp.async / ldmatrix / mma.sync)
// ---------------------------------------------------------------------------
__device__ __forceinline__ uint32_t smem_u32(const void* p) {
    return (uint32_t)__cvta_generic_to_shared(p);
}

__device__ __forceinline__ void cp16(uint32_t dst, const void* src) {
    asm volatile("cp.async.cg.shared.global [%0], [%1], 16;"
                 :: "r"(dst), "l"(src) : "memory");
}
__device__ __forceinline__ void cp_commit() {
    asm volatile("cp.async.commit_group;" ::: "memory");
}
template <int N>
__device__ __forceinline__ void cp_wait() {
    asm volatile("cp.async.wait_group %0;" :: "n"(N) : "memory");
}

__device__ __forceinline__ void ldsm4(uint32_t* r, uint32_t a) {
    asm volatile("ldmatrix.sync.aligned.m8n8.x4.shared.b16 {%0,%1,%2,%3}, [%4];"
                 : "=r"(r[0]), "=r"(r[1]), "=r"(r[2]), "=r"(r[3]) : "r"(a));
}

__device__ __forceinline__ void mma_bf16(float* c, const uint32_t* a,
                                         uint32_t b0, uint32_t b1) {
    asm volatile(
        "mma.sync.aligned.m16n8k16.row.col.f32.bf16.bf16.f32 "
        "{%0,%1,%2,%3}, {%4,%5,%6,%7}, {%8,%9}, {%0,%1,%2,%3};"
        : "+f"(c[0]), "+f"(c[1]), "+f"(c[2]), "+f"(c[3])
        : "r"(a[0]), "r"(a[1]), "r"(a[2]), "r"(a[3]), "r"(b0), "r"(b1));
}

// Swizzled smem offset for a 16B chunk: rows of 64 B, chunk c in 0..3.
// c' = c ^ ((row>>1)&3): conflict-free for both cp.async stores and ldmatrix.
__device__ __forceinline__ uint32_t sw_off(int row, int c) {
    return (uint32_t)(row * 64 + ((c ^ ((row >> 1) & 3)) << 4));
}

// ---------------------------------------------------------------------------
// Prep kernels
// ---------------------------------------------------------------------------
__global__ void prep_w_kernel(const float* __restrict__ A, const float* __restrict__ B) {
    int id = blockIdx.x * blockDim.x + threadIdx.x;   // 1048576
    float a = A[id], b = B[id];
    float w = a - b;
    __nv_bfloat16 wh = __float2bfloat16(w);
    g_Whi[id] = wh;
    g_Wlo[id] = __float2bfloat16(w - __bfloat162float(wh));
    __nv_bfloat16 bh = __float2bfloat16(b);
    g_Bhi[id] = bh;
    g_Blo[id] = __float2bfloat16(b - __bfloat162float(bh));
}

__global__ void prep_x_kernel(const float* __restrict__ x) {
    int id = blockIdx.x * blockDim.x + threadIdx.x;   // 4194304 (x4 vec)
    float4 v = reinterpret_cast<const float4*>(x)[id];
    __nv_bfloat16 h0 = __float2bfloat16(v.x), h1 = __float2bfloat16(v.y);
    __nv_bfloat16 h2 = __float2bfloat16(v.z), h3 = __float2bfloat16(v.w);
    __nv_bfloat16 l0 = __float2bfloat16(v.x - __bfloat162float(h0));
    __nv_bfloat16 l1 = __float2bfloat16(v.y - __bfloat162float(h1));
    __nv_bfloat16 l2 = __float2bfloat16(v.z - __bfloat162float(h2));
    __nv_bfloat16 l3 = __float2bfloat16(v.w - __bfloat162float(h3));
    __nv_bfloat162* Hi = reinterpret_cast<__nv_bfloat162*>(g_Xhi);
    __nv_bfloat162* Lo = reinterpret_cast<__nv_bfloat162*>(g_Xlo);
    Hi[2 * id]     = __halves2bfloat162(h0, h1);
    Hi[2 * id + 1] = __halves2bfloat162(h2, h3);
    Lo[2 * id]     = __halves2bfloat162(l0, l1);
    Lo[2 * id + 1] = __halves2bfloat162(l2, l3);
}

__global__ void compute_S_kernel(const float* __restrict__ x) {
    int id = blockIdx.x * blockDim.x + threadIdx.x;   // 2097152
    int b = id >> 9;
    int h = id & (H_DIM - 1);
    const float* xp = x + (size_t)b * (K_BLK * H_DIM) + h;
    float s = 0.f;
#pragma unroll
    for (int k = 0; k < K_BLK; ++k) s += xp[k * H_DIM];
    __nv_bfloat16 hi = __float2bfloat16(s);
    g_Shi[id] = hi;
    g_Slo[id] = __float2bfloat16(s - __bfloat162float(hi));
}

// ---------------------------------------------------------------------------
// mma.sync GEMM: D[BM,BN] = A[M,K] * B[N,K]^T, 3-pass bf16 hi/lo, f32 acc.
// 8 warps (2x4), warp tile 64x32, 4-stage cp.async pipeline.
// MAIN: out[b, g*4096 + kb*512 + p] = D + T[b, n];  else row-major D store.
// ---------------------------------------------------------------------------
template <bool MAIN>
__global__ void __launch_bounds__(NTHREADS, 1)
mma_gemm_kernel(const __nv_bfloat16* __restrict__ Ahi,
                const __nv_bfloat16* __restrict__ Alo,
                const __nv_bfloat16* __restrict__ Bhi,
                const __nv_bfloat16* __restrict__ Blo,
                const float* __restrict__ Tadd,
                float* __restrict__ outp)
{
    extern __shared__ __align__(128) char smem[];
    const uint32_t sbase = smem_u32(smem);

    const int tid  = threadIdx.x;
    const int lane = tid & 31;
    const int wid  = tid >> 5;
    const int wm   = wid >> 2;          // 0..1  -> 64-row slab
    const int wn   = wid & 3;           // 0..3  -> 32-col slab

    // ---- staging geometry: each thread copies 2 chunks (16 B) per tile ----
    const int r0 = tid >> 2;            // 0..63
    const int r1 = r0 + 64;
    const int c0 = tid & 3;
    const uint32_t d0 = sw_off(r0, c0);
    const uint32_t d1 = sw_off(r1, c0);
    const size_t oA0 = (size_t)(blockIdx.y * BM + r0) * KDIM + c0 * 8;
    const size_t oA1 = (size_t)(blockIdx.y * BM + r1) * KDIM + c0 * 8;
    const size_t oB0 = (size_t)(blockIdx.x * BN + r0) * KDIM + c0 * 8;
    const size_t oB1 = (size_t)(blockIdx.x * BN + r1) * KDIM + c0 * 8;

    // ---- ldmatrix geometry ----
    const int lr = lane & 15;           // row within 16-row fragment
    const int lc = lane >> 4;           // which 16B k-chunk (0/1) of the k16
    uint32_t aoff[4], asw[4];
#pragma unroll
    for (int mf = 0; mf < 4; ++mf) {
        const int row = wm * 64 + mf * 16 + lr;
        aoff[mf] = (uint32_t)(row * 64);
        asw[mf]  = (uint32_t)(((row >> 1) & 3) << 4);
    }
    uint32_t boff[2], bsw[2];
#pragma unroll
    for (int nb = 0; nb < 2; ++nb) {
        const int row = wn * 32 + nb * 16 + lr;
        boff[nb] = (uint32_t)(row * 64);
        bsw[nb]  = (uint32_t)(((row >> 1) & 3) << 4);
    }

    float acc[4][4][4];
#pragma unroll
    for (int i = 0; i < 4; ++i)
#pragma unroll
        for (int j = 0; j < 4; ++j)
#pragma unroll
            for (int e = 0; e < 4; ++e) acc[i][j][e] = 0.f;

    // ---- stage loader ----
    auto load_stage = [&](int s, int kc) {
        const uint32_t sb = sbase + (uint32_t)((s & 3) * STAGE_B);
        const size_t ke = (size_t)kc * BK;
        cp16(sb + d0,              Ahi + oA0 + ke);
        cp16(sb + d1,              Ahi + oA1 + ke);
        cp16(sb + TILE_B + d0,     Alo + oA0 + ke);
        cp16(sb + TILE_B + d1,     Alo + oA1 + ke);
        cp16(sb + 2 * TILE_B + d0, Bhi + oB0 + ke);
        cp16(sb + 2 * TILE_B + d1, Bhi + oB1 + ke);
        cp16(sb + 3 * TILE_B + d0, Blo + oB0 + ke);
        cp16(sb + 3 * TILE_B + d1, Blo + oB1 + ke);
    };

    // ---- prologue: fill stages 0..2 ----
#pragma unroll
    for (int s = 0; s < NSTAGES - 1; ++s) { load_stage(s, s); cp_commit(); }

    // ---- main loop ----
#pragma unroll 1
    for (int kc = 0; kc < KSTEPS; ++kc) {
        if (kc + NSTAGES - 1 < KSTEPS) load_stage(kc + NSTAGES - 1, kc + NSTAGES - 1);
        cp_commit();
        cp_wait<NSTAGES - 1>();        // stage kc resident
        __syncthreads();

        const uint32_t sb = sbase + (uint32_t)((kc & 3) * STAGE_B);
#pragma unroll
        for (int h = 0; h < 2; ++h) {  // two k16 steps per BK=32
            const uint32_t csel = (uint32_t)((2 * h + lc) << 4);
            uint32_t ah[4][4], al[4][4], bh[2][4], bl[2][4];
#pragma unroll
            for (int mf = 0; mf < 4; ++mf) {
                const uint32_t ad = sb + aoff[mf] + (csel ^ asw[mf]);
                ldsm4(ah[mf], ad);
                ldsm4(al[mf], ad + TILE_B);
            }
#pragma unroll
            for (int nb = 0; nb < 2; ++nb) {
                const uint32_t bd = sb + 2 * TILE_B + boff[nb] + (csel ^ bsw[nb]);
                ldsm4(bh[nb], bd);
                ldsm4(bl[nb], bd + TILE_B);
            }
#pragma unroll
            for (int mf = 0; mf < 4; ++mf) {
#pragma unroll
                for (int n8 = 0; n8 < 4; ++n8) {
                    const uint32_t bh0 = bh[n8 >> 1][n8 & 1];
                    const uint32_t bh1 = bh[n8 >> 1][(n8 & 1) + 2];
                    const uint32_t bl0 = bl[n8 >> 1][n8 & 1];
                    const uint32_t bl1 = bl[n8 >> 1][(n8 & 1) + 2];
                    mma_bf16(acc[mf][n8], ah[mf], bh0, bh1);   // hi*hi
                    mma_bf16(acc[mf][n8], ah[mf], bl0, bl1);   // hi*lo
                    mma_bf16(acc[mf][n8], al[mf], bh0, bh1);   // lo*hi
                }
            }
        }
        __syncthreads();               // reads done before buffer reuse
    }

    // ---- epilogue: direct sector-aligned float2 stores ----
    const int m0base = blockIdx.y * BM + wm * 64;
    const int n0base = blockIdx.x * BN + wn * 32;
#pragma unroll
    for (int mf = 0; mf < 4; ++mf) {
#pragma unroll
        for (int n8 = 0; n8 < 4; ++n8) {
            const int n = n0base + n8 * 8 + 2 * (lane & 3);
#pragma unroll
            for (int hf = 0; hf < 2; ++hf) {
                const int m = m0base + mf * 16 + (lane >> 2) + hf * 8;
                float2 v = make_float2(acc[mf][n8][2 * hf], acc[mf][n8][2 * hf + 1]);
                if (MAIN) {
                    const int b  = m >> 3;
                    const int kb = m & 7;
                    const float2 t = *reinterpret_cast<const float2*>(
                        Tadd + (size_t)b * N_COLS + n);
                    v.x += t.x; v.y += t.y;
                    const size_t o = (size_t)b * (G_DIM * K_BLK * H_DIM)
                                   + (size_t)(n >> 9) * (K_BLK * H_DIM)
                                   + (size_t)kb * H_DIM + (n & (H_DIM - 1));
                    *reinterpret_cast<float2*>(outp + o) = v;
                } else {
                    *reinterpret_cast<float2*>(outp + (size_t)m * N_COLS + n) = v;
                }
            }
        }
    }
}

// ---------------------------------------------------------------------------
// Launch
// ---------------------------------------------------------------------------
extern "C" void kernel_launch(void* const* d_in, const int* in_sizes, int n_in,
                              void* d_out, int out_size) {
    const float* x = (const float*)d_in[0];
    const float* A = (const float*)d_in[1];
    const float* B = (const float*)d_in[2];
    float* out = (float*)d_out;

    __nv_bfloat16 *Xhi, *Xlo, *Whi, *Wlo, *Bhi, *Blo, *Shi, *Slo;
    float* T;
    cudaGetSymbolAddress((void**)&Xhi, g_Xhi);
    cudaGetSymbolAddress((void**)&Xlo, g_Xlo);
    cudaGetSymbolAddress((void**)&Whi, g_Whi);
    cudaGetSymbolAddress((void**)&Wlo, g_Wlo);
    cudaGetSymbolAddress((void**)&Bhi, g_Bhi);
    cudaGetSymbolAddress((void**)&Blo, g_Blo);
    cudaGetSymbolAddress((void**)&Shi, g_Shi);
    cudaGetSymbolAddress((void**)&Slo, g_Slo);
    cudaGetSymbolAddress((void**)&T,   g_T);

    cudaFuncSetAttribute(mma_gemm_kernel<true>,
                         cudaFuncAttributeMaxDynamicSharedMemorySize, SMEM_REQ);
    cudaFuncSetAttribute(mma_gemm_kernel<false>,
                         cudaFuncAttributeMaxDynamicSharedMemorySize, SMEM_REQ);

    // 1) weight split (A-B, B) -> bf16 hi/lo
    prep_w_kernel<<<(G_DIM * H_DIM * H_DIM) / 256, 256>>>(A, B);
    // 2) x split -> bf16 hi/lo
    prep_x_kernel<<<(M_MAIN * KDIM / 4) / 256, 256>>>(x);
    // 3) S = sum_k x3, split
    compute_S_kernel<<<(BSZ * H_DIM) / 256, 256>>>(x);
    // 4) T = S @ B^T                      [4096 x 2048]
    mma_gemm_kernel<false><<<dim3(N_COLS / BN, BSZ / BM), NTHREADS, SMEM_REQ>>>(
        Shi, Slo, Bhi, Blo, nullptr, T);
    // 5) out = remap(X @ (A-B)^T + T)     [32768 x 2048]
    mma_gemm_kernel<true><<<dim3(N_COLS / BN, M_MAIN / BM), NTHREADS, SMEM_REQ>>>(
        Xhi, Xlo, Whi, Wlo, T, out);
}

// round 12
// speedup vs baseline: 1.7013x; 1.7013x over previous
#include <cuda_runtime.h>
#include <cuda_fp16.h>
#include <cstdint>

// Problem: x [4096, 4096] fp32, A/B [4, 512, 512] fp32 -> out [4096, 16384] fp32
#define G_DIM 4
#define K_BLK 8
#define H_DIM 512
#define N_COLS 2048            // G*H: GEMM output columns (n = g*512 + p)
#define BSZ 4096
#define M_MAIN 32768           // BSZ * K_BLK
#define KDIM 512

// GEMM tiling (base-ISA mma.sync path — sm_103 has no 'a' features in ptxas)
#define BM 128
#define BN 128
#define BK 32                  // K elems per stage chunk (64 B fp16 rows)
#define KSTEPS (KDIM / BK)     // 16
#define NTHREADS 256
#define NSTAGES 4
#define TILE_B 8192            // 128 rows x 64 B
#define STAGE_B (3 * TILE_B)   // Ah, Bh, Bl = 24 KB
#define SMEM_REQ (NSTAGES * STAGE_B)   // 98304 -> 2 CTAs/SM (192 KB)

// ---------------------------------------------------------------------------
// Static device scratch (no runtime allocation allowed)
// ---------------------------------------------------------------------------
__device__ __half g_Xh[(size_t)M_MAIN * KDIM];   // 32 MB, x in fp16 (single)
__device__ __half g_Wh[(size_t)N_COLS * KDIM];   // (A-B) fp16 hi
__device__ __half g_Wl[(size_t)N_COLS * KDIM];   // (A-B) fp16 lo
__device__ __half g_Bh[(size_t)N_COLS * KDIM];   // B fp16 hi
__device__ __half g_Bl[(size_t)N_COLS * KDIM];   // B fp16 lo
__device__ __half g_Sh[(size_t)BSZ * KDIM];      // sum_k x3, fp16
__device__ float  g_T [(size_t)BSZ * N_COLS];    // T = S @ B^T (fp32)

// ---------------------------------------------------------------------------
// Base-ISA PTX helpers (cp.async / ldmatrix / mma.sync)
// ---------------------------------------------------------------------------
__device__ __forceinline__ uint32_t smem_u32(const void* p) {
    return (uint32_t)__cvta_generic_to_shared(p);
}

__device__ __forceinline__ void cp16(uint32_t dst, const void* src) {
    asm volatile("cp.async.cg.shared.global [%0], [%1], 16;"
                 :: "r"(dst), "l"(src) : "memory");
}
__device__ __forceinline__ void cp_commit() {
    asm volatile("cp.async.commit_group;" ::: "memory");
}
template <int N>
__device__ __forceinline__ void cp_wait() {
    asm volatile("cp.async.wait_group %0;" :: "n"(N) : "memory");
}

__device__ __forceinline__ void ldsm4(uint32_t* r, uint32_t a) {
    asm volatile("ldmatrix.sync.aligned.m8n8.x4.shared.b16 {%0,%1,%2,%3}, [%4];"
                 : "=r"(r[0]), "=r"(r[1]), "=r"(r[2]), "=r"(r[3]) : "r"(a));
}

__device__ __forceinline__ void mma_f16(float* c, const uint32_t* a,
                                        uint32_t b0, uint32_t b1) {
    asm volatile(
        "mma.sync.aligned.m16n8k16.row.col.f32.f16.f16.f32 "
        "{%0,%1,%2,%3}, {%4,%5,%6,%7}, {%8,%9}, {%0,%1,%2,%3};"
        : "+f"(c[0]), "+f"(c[1]), "+f"(c[2]), "+f"(c[3])
        : "r"(a[0]), "r"(a[1]), "r"(a[2]), "r"(a[3]), "r"(b0), "r"(b1));
}

// Swizzled smem offset for a 16B chunk: rows of 64 B, chunk c in 0..3.
__device__ __forceinline__ uint32_t sw_off(int row, int c) {
    return (uint32_t)(row * 64 + ((c ^ ((row >> 1) & 3)) << 4));
}

// ---------------------------------------------------------------------------
// Prep kernels
// ---------------------------------------------------------------------------
// W = A - B; split W and B into fp16 hi/lo (same linear index: no transpose).
__global__ void prep_w_kernel(const float* __restrict__ A, const float* __restrict__ B) {
    int id = blockIdx.x * blockDim.x + threadIdx.x;   // 1048576
    float a = A[id], b = B[id];
    float w = a - b;
    __half wh = __float2half_rn(w);
    g_Wh[id] = wh;
    g_Wl[id] = __float2half_rn(w - __half2float(wh));
    __half bh = __float2half_rn(b);
    g_Bh[id] = bh;
    g_Bl[id] = __float2half_rn(b - __half2float(bh));
}

// x -> fp16 (single word), vectorized
__global__ void prep_x_kernel(const float* __restrict__ x) {
    int id = blockIdx.x * blockDim.x + threadIdx.x;   // 4194304
    float4 v = reinterpret_cast<const float4*>(x)[id];
    __half2* H = reinterpret_cast<__half2*>(g_Xh);
    H[2 * id]     = __floats2half2_rn(v.x, v.y);
    H[2 * id + 1] = __floats2half2_rn(v.z, v.w);
}

// S[b,h] = sum_k x[b, k*512+h] (fp32 accumulate), store fp16
__global__ void compute_S_kernel(const float* __restrict__ x) {
    int id = blockIdx.x * blockDim.x + threadIdx.x;   // 2097152
    int b = id >> 9;
    int h = id & (H_DIM - 1);
    const float* xp = x + (size_t)b * (K_BLK * H_DIM) + h;
    float s = 0.f;
#pragma unroll
    for (int k = 0; k < K_BLK; ++k) s += xp[k * H_DIM];
    g_Sh[id] = __float2half_rn(s);
}

// ---------------------------------------------------------------------------
// mma.sync GEMM: D[BM,BN] = A[M,K] * (Bh+Bl)[N,K]^T, fp16 in, f32 acc.
// 8 warps (2x4), warp tile 64x32, 4-stage cp.async pipeline, 1 sync/iter.
// MAIN: out[b, g*4096 + kb*512 + p] = D + T[b, n];  else row-major D store.
// ---------------------------------------------------------------------------
template <bool MAIN>
__global__ void __launch_bounds__(NTHREADS, 2)
mma_gemm_kernel(const __half* __restrict__ Ah,
                const __half* __restrict__ Bhp,
                const __half* __restrict__ Blp,
                const float* __restrict__ Tadd,
                float* __restrict__ outp)
{
    extern __shared__ __align__(128) char smem[];
    const uint32_t sbase = smem_u32(smem);

    const int tid  = threadIdx.x;
    const int lane = tid & 31;
    const int wid  = tid >> 5;
    const int wm   = wid >> 2;          // 0..1  -> 64-row slab
    const int wn   = wid & 3;           // 0..3  -> 32-col slab

    // ---- staging geometry: each thread copies 2 chunks (16 B) per tile ----
    const int r0 = tid >> 2;            // 0..63
    const int r1 = r0 + 64;
    const int c0 = tid & 3;
    const uint32_t d0 = sw_off(r0, c0);
    const uint32_t d1 = sw_off(r1, c0);
    const size_t oA0 = (size_t)(blockIdx.y * BM + r0) * KDIM + c0 * 8;
    const size_t oA1 = (size_t)(blockIdx.y * BM + r1) * KDIM + c0 * 8;
    const size_t oB0 = (size_t)(blockIdx.x * BN + r0) * KDIM + c0 * 8;
    const size_t oB1 = (size_t)(blockIdx.x * BN + r1) * KDIM + c0 * 8;

    // ---- ldmatrix geometry ----
    const int lr = lane & 15;           // row within 16-row fragment
    const int lc = lane >> 4;           // which 16B k-chunk of the k16
    uint32_t aoff[4], asw[4];
#pragma unroll
    for (int mf = 0; mf < 4; ++mf) {
        const int row = wm * 64 + mf * 16 + lr;
        aoff[mf] = (uint32_t)(row * 64);
        asw[mf]  = (uint32_t)(((row >> 1) & 3) << 4);
    }
    uint32_t boff[2], bsw[2];
#pragma unroll
    for (int nb = 0; nb < 2; ++nb) {
        const int row = wn * 32 + nb * 16 + lr;
        boff[nb] = (uint32_t)(row * 64);
        bsw[nb]  = (uint32_t)(((row >> 1) & 3) << 4);
    }

    float acc[4][4][4];
#pragma unroll
    for (int i = 0; i < 4; ++i)
#pragma unroll
        for (int j = 0; j < 4; ++j)
#pragma unroll
            for (int e = 0; e < 4; ++e) acc[i][j][e] = 0.f;

    // ---- stage loader: Ah | Bh | Bl (24 KB) ----
    auto load_stage = [&](int s, int kc) {
        const uint32_t sb = sbase + (uint32_t)((s & 3) * STAGE_B);
        const size_t ke = (size_t)kc * BK;
        cp16(sb + d0,              Ah  + oA0 + ke);
        cp16(sb + d1,              Ah  + oA1 + ke);
        cp16(sb + TILE_B + d0,     Bhp + oB0 + ke);
        cp16(sb + TILE_B + d1,     Bhp + oB1 + ke);
        cp16(sb + 2 * TILE_B + d0, Blp + oB0 + ke);
        cp16(sb + 2 * TILE_B + d1, Blp + oB1 + ke);
    };

    // ---- prologue: fill stages 0..2 ----
#pragma unroll
    for (int s = 0; s < NSTAGES - 1; ++s) { load_stage(s, s); cp_commit(); }

    // ---- main loop: ONE syncthreads per iteration ----
    // Order: wait(stage kc) -> sync -> issue loads for stage kc+3 -> compute kc.
    // The sync orders iter kc-1's reads of stage (kc-1)&3 before this iter's
    // overwrite of that same buffer.
#pragma unroll 1
    for (int kc = 0; kc < KSTEPS; ++kc) {
        cp_wait<NSTAGES - 2>();        // stage kc resident
        __syncthreads();
        if (kc + NSTAGES - 1 < KSTEPS) load_stage(kc + NSTAGES - 1, kc + NSTAGES - 1);
        cp_commit();

        const uint32_t sb = sbase + (uint32_t)((kc & 3) * STAGE_B);
#pragma unroll
        for (int h = 0; h < 2; ++h) {  // two k16 steps per BK=32
            const uint32_t csel = (uint32_t)((2 * h + lc) << 4);
            uint32_t af[4][4], bh[2][4], bl[2][4];
#pragma unroll
            for (int mf = 0; mf < 4; ++mf)
                ldsm4(af[mf], sb + aoff[mf] + (csel ^ asw[mf]));
#pragma unroll
            for (int nb = 0; nb < 2; ++nb) {
                const uint32_t bd = sb + TILE_B + boff[nb] + (csel ^ bsw[nb]);
                ldsm4(bh[nb], bd);
                ldsm4(bl[nb], bd + TILE_B);
            }
#pragma unroll
            for (int mf = 0; mf < 4; ++mf) {
#pragma unroll
                for (int n8 = 0; n8 < 4; ++n8) {
                    const uint32_t bh0 = bh[n8 >> 1][n8 & 1];
                    const uint32_t bh1 = bh[n8 >> 1][(n8 & 1) + 2];
                    const uint32_t bl0 = bl[n8 >> 1][n8 & 1];
                    const uint32_t bl1 = bl[n8 >> 1][(n8 & 1) + 2];
                    mma_f16(acc[mf][n8], af[mf], bh0, bh1);   // x * W_hi
                    mma_f16(acc[mf][n8], af[mf], bl0, bl1);   // x * W_lo
                }
            }
        }
    }

    // ---- epilogue: direct sector-aligned float2 stores ----
    const int m0base = blockIdx.y * BM + wm * 64;
    const int n0base = blockIdx.x * BN + wn * 32;
#pragma unroll
    for (int mf = 0; mf < 4; ++mf) {
#pragma unroll
        for (int n8 = 0; n8 < 4; ++n8) {
            const int n = n0base + n8 * 8 + 2 * (lane & 3);
#pragma unroll
            for (int hf = 0; hf < 2; ++hf) {
                const int m = m0base + mf * 16 + (lane >> 2) + hf * 8;
                float2 v = make_float2(acc[mf][n8][2 * hf], acc[mf][n8][2 * hf + 1]);
                if (MAIN) {
                    const int b  = m >> 3;
                    const int kb = m & 7;
                    const float2 t = *reinterpret_cast<const float2*>(
                        Tadd + (size_t)b * N_COLS + n);
                    v.x += t.x; v.y += t.y;
                    const size_t o = (size_t)b * (G_DIM * K_BLK * H_DIM)
                                   + (size_t)(n >> 9) * (K_BLK * H_DIM)
                                   + (size_t)kb * H_DIM + (n & (H_DIM - 1));
                    *reinterpret_cast<float2*>(outp + o) = v;
                } else {
                    *reinterpret_cast<float2*>(outp + (size_t)m * N_COLS + n) = v;
                }
            }
        }
    }
}

// ---------------------------------------------------------------------------
// Launch
// ---------------------------------------------------------------------------
extern "C" void kernel_launch(void* const* d_in, const int* in_sizes, int n_in,
                              void* d_out, int out_size) {
    const float* x = (const float*)d_in[0];
    const float* A = (const float*)d_in[1];
    const float* B = (const float*)d_in[2];
    float* out = (float*)d_out;

    __half *Xh, *Wh, *Wl, *Bh, *Bl, *Sh;
    float* T;
    cudaGetSymbolAddress((void**)&Xh, g_Xh);
    cudaGetSymbolAddress((void**)&Wh, g_Wh);
    cudaGetSymbolAddress((void**)&Wl, g_Wl);
    cudaGetSymbolAddress((void**)&Bh, g_Bh);
    cudaGetSymbolAddress((void**)&Bl, g_Bl);
    cudaGetSymbolAddress((void**)&Sh, g_Sh);
    cudaGetSymbolAddress((void**)&T,  g_T);

    cudaFuncSetAttribute(mma_gemm_kernel<true>,
                         cudaFuncAttributeMaxDynamicSharedMemorySize, SMEM_REQ);
    cudaFuncSetAttribute(mma_gemm_kernel<false>,
                         cudaFuncAttributeMaxDynamicSharedMemorySize, SMEM_REQ);

    // 1) W = A-B; split W, B -> fp16 hi/lo
    prep_w_kernel<<<(G_DIM * H_DIM * H_DIM) / 256, 256>>>(A, B);
    // 2) x -> fp16
    prep_x_kernel<<<(M_MAIN * KDIM / 4) / 256, 256>>>(x);
    // 3) S = sum_k x3 -> fp16
    compute_S_kernel<<<(BSZ * H_DIM) / 256, 256>>>(x);
    // 4) T = S @ (Bh+Bl)^T                [4096 x 2048]
    mma_gemm_kernel<false><<<dim3(N_COLS / BN, BSZ / BM), NTHREADS, SMEM_REQ>>>(
        Sh, Bh, Bl, nullptr, T);
    // 5) out = remap(X @ (Wh+Wl)^T + T)   [32768 x 2048]
    mma_gemm_kernel<true><<<dim3(N_COLS / BN, M_MAIN / BM), NTHREADS, SMEM_REQ>>>(
        Xh, Wh, Wl, T, out);
}

// round 13
// speedup vs baseline: 2.4465x; 1.4381x over previous
#include <cuda_runtime.h>
#include <cuda_fp16.h>
#include <cstdint>

// Problem: x [4096, 4096] fp32, A/B [4, 512, 512] fp32 -> out [4096, 16384] fp32
#define G_DIM 4
#define K_BLK 8
#define H_DIM 512
#define N_COLS 2048            // G*H: GEMM output columns (n = g*512 + p)
#define BSZ 4096
#define M_MAIN 32768           // BSZ * K_BLK
#define KDIM 512

// GEMM tiling (base-ISA mma.sync path — sm_103 ptxas has no 'a' features)
#define BM 128
#define BN 128
#define BK 32                  // K elems per stage chunk (64 B fp16 rows)
#define KSTEPS (KDIM / BK)     // 16
#define NTHREADS 256
#define NSTAGES 4
#define TILE_B 8192            // 128 rows x 64 B

// ---------------------------------------------------------------------------
// Static device scratch (no runtime allocation allowed)
// ---------------------------------------------------------------------------
__device__ __half g_Xh[(size_t)M_MAIN * KDIM];   // 32 MB, x fp16
__device__ __half g_Wh[(size_t)N_COLS * KDIM];   // (A-B) fp16 (single)
__device__ __half g_Bh[(size_t)N_COLS * KDIM];   // B fp16 hi
__device__ __half g_Bl[(size_t)N_COLS * KDIM];   // B fp16 lo
__device__ __half g_Sh[(size_t)BSZ * KDIM];      // sum_k x3, fp16
__device__ float  g_T [(size_t)BSZ * N_COLS];    // T = S @ B^T (fp32)

// ---------------------------------------------------------------------------
// Base-ISA PTX helpers (cp.async / ldmatrix / mma.sync)
// ---------------------------------------------------------------------------
__device__ __forceinline__ uint32_t smem_u32(const void* p) {
    return (uint32_t)__cvta_generic_to_shared(p);
}

__device__ __forceinline__ void cp16(uint32_t dst, const void* src) {
    asm volatile("cp.async.cg.shared.global [%0], [%1], 16;"
                 :: "r"(dst), "l"(src) : "memory");
}
__device__ __forceinline__ void cp_commit() {
    asm volatile("cp.async.commit_group;" ::: "memory");
}
template <int N>
__device__ __forceinline__ void cp_wait() {
    asm volatile("cp.async.wait_group %0;" :: "n"(N) : "memory");
}

__device__ __forceinline__ void ldsm4(uint32_t* r, uint32_t a) {
    asm volatile("ldmatrix.sync.aligned.m8n8.x4.shared.b16 {%0,%1,%2,%3}, [%4];"
                 : "=r"(r[0]), "=r"(r[1]), "=r"(r[2]), "=r"(r[3]) : "r"(a));
}

__device__ __forceinline__ void mma_f16(float* c, const uint32_t* a,
                                        uint32_t b0, uint32_t b1) {
    asm volatile(
        "mma.sync.aligned.m16n8k16.row.col.f32.f16.f16.f32 "
        "{%0,%1,%2,%3}, {%4,%5,%6,%7}, {%8,%9}, {%0,%1,%2,%3};"
        : "+f"(c[0]), "+f"(c[1]), "+f"(c[2]), "+f"(c[3])
        : "r"(a[0]), "r"(a[1]), "r"(a[2]), "r"(a[3]), "r"(b0), "r"(b1));
}

// Swizzled smem offset for a 16B chunk: rows of 64 B, chunk c in 0..3.
__device__ __forceinline__ uint32_t sw_off(int row, int c) {
    return (uint32_t)(row * 64 + ((c ^ ((row >> 1) & 3)) << 4));
}

// ---------------------------------------------------------------------------
// Prep kernels
// ---------------------------------------------------------------------------
// W = A - B -> single fp16; B -> fp16 hi/lo (T path keeps 2-pass accuracy).
__global__ void prep_w_kernel(const float* __restrict__ A, const float* __restrict__ B) {
    int id = blockIdx.x * blockDim.x + threadIdx.x;   // 1048576
    float a = A[id], b = B[id];
    g_Wh[id] = __float2half_rn(a - b);
    __half bh = __float2half_rn(b);
    g_Bh[id] = bh;
    g_Bl[id] = __float2half_rn(b - __half2float(bh));
}

// x -> fp16, vectorized
__global__ void prep_x_kernel(const float* __restrict__ x) {
    int id = blockIdx.x * blockDim.x + threadIdx.x;   // 4194304
    float4 v = reinterpret_cast<const float4*>(x)[id];
    __half2* H = reinterpret_cast<__half2*>(g_Xh);
    H[2 * id]     = __floats2half2_rn(v.x, v.y);
    H[2 * id + 1] = __floats2half2_rn(v.z, v.w);
}

// S[b,h] = sum_k x[b, k*512+h] (fp32 accumulate), store fp16
__global__ void compute_S_kernel(const float* __restrict__ x) {
    int id = blockIdx.x * blockDim.x + threadIdx.x;   // 2097152
    int b = id >> 9;
    int h = id & (H_DIM - 1);
    const float* xp = x + (size_t)b * (K_BLK * H_DIM) + h;
    float s = 0.f;
#pragma unroll
    for (int k = 0; k < K_BLK; ++k) s += xp[k * H_DIM];
    g_Sh[id] = __float2half_rn(s);
}

// ---------------------------------------------------------------------------
// mma.sync GEMM: D[BM,BN] = A[M,K] * B[N,K]^T, fp16 in, f32 acc.
//   TWOPASS: B = Bh + Bl (two MMA passes);  else single pass (B = Bh).
// 8 warps (2x4), warp tile 64x32, 4-stage cp.async pipeline, 1 sync/iter.
// MAIN: out[b, g*4096 + kb*512 + p] = D + T[b, n];  else row-major D store.
// ---------------------------------------------------------------------------
template <bool MAIN, bool TWOPASS>
__global__ void __launch_bounds__(NTHREADS, 2)
mma_gemm_kernel(const __half* __restrict__ Ah,
                const __half* __restrict__ Bhp,
                const __half* __restrict__ Blp,
                const float* __restrict__ Tadd,
                float* __restrict__ outp)
{
    constexpr int NTILES  = TWOPASS ? 3 : 2;          // A, Bh[, Bl]
    constexpr int STAGE_B = NTILES * TILE_B;

    extern __shared__ __align__(128) char smem[];
    const uint32_t sbase = smem_u32(smem);

    const int tid  = threadIdx.x;
    const int lane = tid & 31;
    const int wid  = tid >> 5;
    const int wm   = wid >> 2;          // 0..1  -> 64-row slab
    const int wn   = wid & 3;           // 0..3  -> 32-col slab

    // ---- staging geometry: each thread copies 2 chunks (16 B) per tile ----
    const int r0 = tid >> 2;            // 0..63
    const int r1 = r0 + 64;
    const int c0 = tid & 3;
    const uint32_t d0 = sw_off(r0, c0);
    const uint32_t d1 = sw_off(r1, c0);
    const size_t oA0 = (size_t)(blockIdx.y * BM + r0) * KDIM + c0 * 8;
    const size_t oA1 = (size_t)(blockIdx.y * BM + r1) * KDIM + c0 * 8;
    const size_t oB0 = (size_t)(blockIdx.x * BN + r0) * KDIM + c0 * 8;
    const size_t oB1 = (size_t)(blockIdx.x * BN + r1) * KDIM + c0 * 8;

    // ---- ldmatrix geometry ----
    const int lr = lane & 15;           // row within 16-row fragment
    const int lc = lane >> 4;           // which 16B k-chunk of the k16
    uint32_t aoff[4], asw[4];
#pragma unroll
    for (int mf = 0; mf < 4; ++mf) {
        const int row = wm * 64 + mf * 16 + lr;
        aoff[mf] = (uint32_t)(row * 64);
        asw[mf]  = (uint32_t)(((row >> 1) & 3) << 4);
    }
    uint32_t boff[2], bsw[2];
#pragma unroll
    for (int nb = 0; nb < 2; ++nb) {
        const int row = wn * 32 + nb * 16 + lr;
        boff[nb] = (uint32_t)(row * 64);
        bsw[nb]  = (uint32_t)(((row >> 1) & 3) << 4);
    }

    float acc[4][4][4];
#pragma unroll
    for (int i = 0; i < 4; ++i)
#pragma unroll
        for (int j = 0; j < 4; ++j)
#pragma unroll
            for (int e = 0; e < 4; ++e) acc[i][j][e] = 0.f;

    // ---- stage loader ----
    auto load_stage = [&](int s, int kc) {
        const uint32_t sb = sbase + (uint32_t)((s & 3) * STAGE_B);
        const size_t ke = (size_t)kc * BK;
        cp16(sb + d0,          Ah  + oA0 + ke);
        cp16(sb + d1,          Ah  + oA1 + ke);
        cp16(sb + TILE_B + d0, Bhp + oB0 + ke);
        cp16(sb + TILE_B + d1, Bhp + oB1 + ke);
        if (TWOPASS) {
            cp16(sb + 2 * TILE_B + d0, Blp + oB0 + ke);
            cp16(sb + 2 * TILE_B + d1, Blp + oB1 + ke);
        }
    };

    // ---- prologue: fill stages 0..2 ----
#pragma unroll
    for (int s = 0; s < NSTAGES - 1; ++s) { load_stage(s, s); cp_commit(); }

    // ---- main loop: ONE syncthreads per iteration ----
#pragma unroll 1
    for (int kc = 0; kc < KSTEPS; ++kc) {
        cp_wait<NSTAGES - 2>();        // stage kc resident
        __syncthreads();
        if (kc + NSTAGES - 1 < KSTEPS) load_stage(kc + NSTAGES - 1, kc + NSTAGES - 1);
        cp_commit();

        const uint32_t sb = sbase + (uint32_t)((kc & 3) * STAGE_B);
#pragma unroll
        for (int h = 0; h < 2; ++h) {  // two k16 steps per BK=32
            const uint32_t csel = (uint32_t)((2 * h + lc) << 4);
            uint32_t af[4][4], bh[2][4], bl[2][4];
#pragma unroll
            for (int mf = 0; mf < 4; ++mf)
                ldsm4(af[mf], sb + aoff[mf] + (csel ^ asw[mf]));
#pragma unroll
            for (int nb = 0; nb < 2; ++nb) {
                const uint32_t bd = sb + TILE_B + boff[nb] + (csel ^ bsw[nb]);
                ldsm4(bh[nb], bd);
                if (TWOPASS) ldsm4(bl[nb], bd + TILE_B);
            }
#pragma unroll
            for (int mf = 0; mf < 4; ++mf) {
#pragma unroll
                for (int n8 = 0; n8 < 4; ++n8) {
                    const uint32_t bh0 = bh[n8 >> 1][n8 & 1];
                    const uint32_t bh1 = bh[n8 >> 1][(n8 & 1) + 2];
                    mma_f16(acc[mf][n8], af[mf], bh0, bh1);
                    if (TWOPASS) {
                        const uint32_t bl0 = bl[n8 >> 1][n8 & 1];
                        const uint32_t bl1 = bl[n8 >> 1][(n8 & 1) + 2];
                        mma_f16(acc[mf][n8], af[mf], bl0, bl1);
                    }
                }
            }
        }
    }

    // ---- epilogue: direct sector-aligned float2 stores ----
    const int m0base = blockIdx.y * BM + wm * 64;
    const int n0base = blockIdx.x * BN + wn * 32;
#pragma unroll
    for (int mf = 0; mf < 4; ++mf) {
#pragma unroll
        for (int n8 = 0; n8 < 4; ++n8) {
            const int n = n0base + n8 * 8 + 2 * (lane & 3);
#pragma unroll
            for (int hf = 0; hf < 2; ++hf) {
                const int m = m0base + mf * 16 + (lane >> 2) + hf * 8;
                float2 v = make_float2(acc[mf][n8][2 * hf], acc[mf][n8][2 * hf + 1]);
                if (MAIN) {
                    const int b  = m >> 3;
                    const int kb = m & 7;
                    const float2 t = *reinterpret_cast<const float2*>(
                        Tadd + (size_t)b * N_COLS + n);
                    v.x += t.x; v.y += t.y;
                    const size_t o = (size_t)b * (G_DIM * K_BLK * H_DIM)
                                   + (size_t)(n >> 9) * (K_BLK * H_DIM)
                                   + (size_t)kb * H_DIM + (n & (H_DIM - 1));
                    *reinterpret_cast<float2*>(outp + o) = v;
                } else {
                    *reinterpret_cast<float2*>(outp + (size_t)m * N_COLS + n) = v;
                }
            }
        }
    }
}

// ---------------------------------------------------------------------------
// Launch
// ---------------------------------------------------------------------------
extern "C" void kernel_launch(void* const* d_in, const int* in_sizes, int n_in,
                              void* d_out, int out_size) {
    const float* x = (const float*)d_in[0];
    const float* A = (const float*)d_in[1];
    const float* B = (const float*)d_in[2];
    float* out = (float*)d_out;

    __half *Xh, *Wh, *Bh, *Bl, *Sh;
    float* T;
    cudaGetSymbolAddress((void**)&Xh, g_Xh);
    cudaGetSymbolAddress((void**)&Wh, g_Wh);
    cudaGetSymbolAddress((void**)&Bh, g_Bh);
    cudaGetSymbolAddress((void**)&Bl, g_Bl);
    cudaGetSymbolAddress((void**)&Sh, g_Sh);
    cudaGetSymbolAddress((void**)&T,  g_T);

    constexpr int SMEM_T    = NSTAGES * 3 * TILE_B;   // 96 KB (2-pass)
    constexpr int SMEM_MAIN = NSTAGES * 2 * TILE_B;   // 64 KB (1-pass)
    cudaFuncSetAttribute(mma_gemm_kernel<false, true>,
                         cudaFuncAttributeMaxDynamicSharedMemorySize, SMEM_T);
    cudaFuncSetAttribute(mma_gemm_kernel<true, false>,
                         cudaFuncAttributeMaxDynamicSharedMemorySize, SMEM_MAIN);

    // 1) W = A-B (fp16); B -> fp16 hi/lo
    prep_w_kernel<<<(G_DIM * H_DIM * H_DIM) / 256, 256>>>(A, B);
    // 2) x -> fp16
    prep_x_kernel<<<(M_MAIN * KDIM / 4) / 256, 256>>>(x);
    // 3) S = sum_k x3 -> fp16
    compute_S_kernel<<<(BSZ * H_DIM) / 256, 256>>>(x);
    // 4) T = S @ (Bh+Bl)^T  (2-pass, accurate)   [4096 x 2048]
    mma_gemm_kernel<false, true><<<dim3(N_COLS / BN, BSZ / BM), NTHREADS, SMEM_T>>>(
        Sh, Bh, Bl, nullptr, T);
    // 5) out = remap(X @ W^T + T)  (1-pass)      [32768 x 2048]
    mma_gemm_kernel<true, false><<<dim3(N_COLS / BN, M_MAIN / BM), NTHREADS, SMEM_MAIN>>>(
        Xh, Wh, nullptr, T, out);
}

// round 14
// speedup vs baseline: 2.7308x; 1.1162x over previous
#include <cuda_runtime.h>
#include <cuda_fp16.h>
#include <cstdint>

// Problem: x [4096, 4096] fp32, A/B [4, 512, 512] fp32 -> out [4096, 16384] fp32
#define G_DIM 4
#define K_BLK 8
#define H_DIM 512
#define N_COLS 2048            // G*H: GEMM output columns (n = g*512 + p)
#define BSZ 4096
#define M_MAIN 32768           // BSZ * K_BLK
#define KDIM 512

// GEMM tiling (base-ISA mma.sync path — sm_103 ptxas has no 'a' features)
#define BM 64                  // CTA rows
#define BN 128                 // CTA cols
#define BK 32                  // K elems per stage chunk (64 B fp16 rows)
#define KSTEPS (KDIM / BK)     // 16
#define NTHREADS 256
#define NSTAGES 4
#define ATILE_B 4096           // 64 rows x 64 B
#define BTILE_B 8192           // 128 rows x 64 B
#define STAGE_B (ATILE_B + BTILE_B)        // 12 KB
#define SMEM_REQ (NSTAGES * STAGE_B)       // 48 KB -> 3 CTAs/SM (144 KB)

// ---------------------------------------------------------------------------
// Static device scratch (no runtime allocation allowed)
// ---------------------------------------------------------------------------
__device__ __half g_Xh[(size_t)M_MAIN * KDIM];   // 32 MB, x fp16
__device__ __half g_Wh[(size_t)N_COLS * KDIM];   // (A-B) fp16
__device__ __half g_Bh[(size_t)N_COLS * KDIM];   // B fp16
__device__ __half g_Sh[(size_t)BSZ * KDIM];      // sum_k x3, fp16
__device__ float  g_T [(size_t)BSZ * N_COLS];    // T = S @ B^T (fp32)

// ---------------------------------------------------------------------------
// Base-ISA PTX helpers (cp.async / ldmatrix / mma.sync)
// ---------------------------------------------------------------------------
__device__ __forceinline__ uint32_t smem_u32(const void* p) {
    return (uint32_t)__cvta_generic_to_shared(p);
}

__device__ __forceinline__ void cp16(uint32_t dst, const void* src) {
    asm volatile("cp.async.cg.shared.global [%0], [%1], 16;"
                 :: "r"(dst), "l"(src) : "memory");
}
__device__ __forceinline__ void cp_commit() {
    asm volatile("cp.async.commit_group;" ::: "memory");
}
template <int N>
__device__ __forceinline__ void cp_wait() {
    asm volatile("cp.async.wait_group %0;" :: "n"(N) : "memory");
}

__device__ __forceinline__ void ldsm4(uint32_t* r, uint32_t a) {
    asm volatile("ldmatrix.sync.aligned.m8n8.x4.shared.b16 {%0,%1,%2,%3}, [%4];"
                 : "=r"(r[0]), "=r"(r[1]), "=r"(r[2]), "=r"(r[3]) : "r"(a));
}

__device__ __forceinline__ void mma_f16(float* c, const uint32_t* a,
                                        uint32_t b0, uint32_t b1) {
    asm volatile(
        "mma.sync.aligned.m16n8k16.row.col.f32.f16.f16.f32 "
        "{%0,%1,%2,%3}, {%4,%5,%6,%7}, {%8,%9}, {%0,%1,%2,%3};"
        : "+f"(c[0]), "+f"(c[1]), "+f"(c[2]), "+f"(c[3])
        : "r"(a[0]), "r"(a[1]), "r"(a[2]), "r"(a[3]), "r"(b0), "r"(b1));
}

// Swizzled smem offset for a 16B chunk: rows of 64 B, chunk c in 0..3.
__device__ __forceinline__ uint32_t sw_off(int row, int c) {
    return (uint32_t)(row * 64 + ((c ^ ((row >> 1) & 3)) << 4));
}

// ---------------------------------------------------------------------------
// Prep kernels
// ---------------------------------------------------------------------------
// W = A - B -> fp16; B -> fp16 (both single precision halves)
__global__ void prep_w_kernel(const float* __restrict__ A, const float* __restrict__ B) {
    int id = blockIdx.x * blockDim.x + threadIdx.x;   // 1048576
    float a = A[id], b = B[id];
    g_Wh[id] = __float2half_rn(a - b);
    g_Bh[id] = __float2half_rn(b);
}

// Fused: x -> fp16 AND S[b,h] = sum_k x[b, k*512+h] (fp32 acc) -> fp16.
// One block per batch row; reads x exactly once.
__global__ void prep_x_s_kernel(const float* __restrict__ x) {
    const int b = blockIdx.x;            // 0..4095
    const int h = threadIdx.x;           // 0..511
    const float* xr = x + (size_t)b * (K_BLK * H_DIM);
    __half* xo = g_Xh + (size_t)b * (K_BLK * H_DIM);
    float s = 0.f;
#pragma unroll
    for (int k = 0; k < K_BLK; ++k) {
        float v = xr[k * H_DIM + h];
        s += v;
        xo[k * H_DIM + h] = __float2half_rn(v);
    }
    g_Sh[(size_t)b * H_DIM + h] = __float2half_rn(s);
}

// ---------------------------------------------------------------------------
// mma.sync GEMM: D[64,128] per CTA = A[M,K] * B[N,K]^T, fp16 in, f32 acc.
// 8 warps (2x4), warp tile 32x32, 4-stage cp.async pipeline, 1 sync/iter.
// MAIN: out[b, g*4096 + kb*512 + p] = D + T[b, n];  else row-major D store.
// ---------------------------------------------------------------------------
template <bool MAIN>
__global__ void __launch_bounds__(NTHREADS, 3)
mma_gemm_kernel(const __half* __restrict__ Ap,
                const __half* __restrict__ Bp,
                const float* __restrict__ Tadd,
                float* __restrict__ outp)
{
    extern __shared__ __align__(128) char smem[];
    const uint32_t sbase = smem_u32(smem);

    const int tid  = threadIdx.x;
    const int lane = tid & 31;
    const int wid  = tid >> 5;
    const int wm   = wid >> 2;          // 0..1  -> 32-row slab
    const int wn   = wid & 3;           // 0..3  -> 32-col slab

    // ---- staging geometry ----
    // A: 64 rows x 4 chunks = 256 -> 1 chunk/thread
    // B: 128 rows x 4 chunks = 512 -> 2 chunks/thread
    const int r0 = tid >> 2;            // 0..63
    const int c0 = tid & 3;
    const uint32_t dA  = sw_off(r0, c0);
    const uint32_t dB0 = dA;            // same formula, rows 0..63
    const uint32_t dB1 = sw_off(r0 + 64, c0);
    const size_t oA  = (size_t)(blockIdx.y * BM + r0) * KDIM + c0 * 8;
    const size_t oB0 = (size_t)(blockIdx.x * BN + r0) * KDIM + c0 * 8;
    const size_t oB1 = (size_t)(blockIdx.x * BN + r0 + 64) * KDIM + c0 * 8;

    // ---- ldmatrix geometry ----
    const int lr = lane & 15;           // row within 16-row fragment
    const int lc = lane >> 4;           // which 16B k-chunk of the k16
    uint32_t aoff[2], asw[2];
#pragma unroll
    for (int mf = 0; mf < 2; ++mf) {
        const int row = wm * 32 + mf * 16 + lr;
        aoff[mf] = (uint32_t)(row * 64);
        asw[mf]  = (uint32_t)(((row >> 1) & 3) << 4);
    }
    uint32_t boff[2], bsw[2];
#pragma unroll
    for (int nb = 0; nb < 2; ++nb) {
        const int row = wn * 32 + nb * 16 + lr;
        boff[nb] = (uint32_t)(ATILE_B + row * 64);
        bsw[nb]  = (uint32_t)(((row >> 1) & 3) << 4);
    }

    float acc[2][4][4];
#pragma unroll
    for (int i = 0; i < 2; ++i)
#pragma unroll
        for (int j = 0; j < 4; ++j)
#pragma unroll
            for (int e = 0; e < 4; ++e) acc[i][j][e] = 0.f;

    // ---- stage loader: A (4 KB) | B (8 KB) ----
    auto load_stage = [&](int s, int kc) {
        const uint32_t sb = sbase + (uint32_t)((s & 3) * STAGE_B);
        const size_t ke = (size_t)kc * BK;
        cp16(sb + dA,            Ap + oA  + ke);
        cp16(sb + ATILE_B + dB0, Bp + oB0 + ke);
        cp16(sb + ATILE_B + dB1, Bp + oB1 + ke);
    };

    // ---- prologue: fill stages 0..2 ----
#pragma unroll
    for (int s = 0; s < NSTAGES - 1; ++s) { load_stage(s, s); cp_commit(); }

    // ---- main loop: one syncthreads per iteration ----
#pragma unroll 1
    for (int kc = 0; kc < KSTEPS; ++kc) {
        cp_wait<NSTAGES - 2>();        // stage kc resident
        __syncthreads();
        if (kc + NSTAGES - 1 < KSTEPS) load_stage(kc + NSTAGES - 1, kc + NSTAGES - 1);
        cp_commit();

        const uint32_t sb = sbase + (uint32_t)((kc & 3) * STAGE_B);
#pragma unroll
        for (int h = 0; h < 2; ++h) {  // two k16 steps per BK=32
            const uint32_t csel = (uint32_t)((2 * h + lc) << 4);
            uint32_t af[2][4], bf[2][4];
#pragma unroll
            for (int mf = 0; mf < 2; ++mf)
                ldsm4(af[mf], sb + aoff[mf] + (csel ^ asw[mf]));
#pragma unroll
            for (int nb = 0; nb < 2; ++nb)
                ldsm4(bf[nb], sb + boff[nb] + (csel ^ bsw[nb]));
#pragma unroll
            for (int mf = 0; mf < 2; ++mf) {
#pragma unroll
                for (int n8 = 0; n8 < 4; ++n8) {
                    const uint32_t b0 = bf[n8 >> 1][n8 & 1];
                    const uint32_t b1 = bf[n8 >> 1][(n8 & 1) + 2];
                    mma_f16(acc[mf][n8], af[mf], b0, b1);
                }
            }
        }
    }

    // ---- epilogue: direct sector-aligned float2 stores ----
    const int m0base = blockIdx.y * BM + wm * 32;
    const int n0base = blockIdx.x * BN + wn * 32;
#pragma unroll
    for (int mf = 0; mf < 2; ++mf) {
#pragma unroll
        for (int n8 = 0; n8 < 4; ++n8) {
            const int n = n0base + n8 * 8 + 2 * (lane & 3);
#pragma unroll
            for (int hf = 0; hf < 2; ++hf) {
                const int m = m0base + mf * 16 + (lane >> 2) + hf * 8;
                float2 v = make_float2(acc[mf][n8][2 * hf], acc[mf][n8][2 * hf + 1]);
                if (MAIN) {
                    const int b  = m >> 3;
                    const int kb = m & 7;
                    const float2 t = *reinterpret_cast<const float2*>(
                        Tadd + (size_t)b * N_COLS + n);
                    v.x += t.x; v.y += t.y;
                    const size_t o = (size_t)b * (G_DIM * K_BLK * H_DIM)
                                   + (size_t)(n >> 9) * (K_BLK * H_DIM)
                                   + (size_t)kb * H_DIM + (n & (H_DIM - 1));
                    *reinterpret_cast<float2*>(outp + o) = v;
                } else {
                    *reinterpret_cast<float2*>(outp + (size_t)m * N_COLS + n) = v;
                }
            }
        }
    }
}

// ---------------------------------------------------------------------------
// Launch
// ---------------------------------------------------------------------------
extern "C" void kernel_launch(void* const* d_in, const int* in_sizes, int n_in,
                              void* d_out, int out_size) {
    const float* x = (const float*)d_in[0];
    const float* A = (const float*)d_in[1];
    const float* B = (const float*)d_in[2];
    float* out = (float*)d_out;

    __half *Xh, *Wh, *Bh, *Sh;
    float* T;
    cudaGetSymbolAddress((void**)&Xh, g_Xh);
    cudaGetSymbolAddress((void**)&Wh, g_Wh);
    cudaGetSymbolAddress((void**)&Bh, g_Bh);
    cudaGetSymbolAddress((void**)&Sh, g_Sh);
    cudaGetSymbolAddress((void**)&T,  g_T);

    cudaFuncSetAttribute(mma_gemm_kernel<false>,
                         cudaFuncAttributeMaxDynamicSharedMemorySize, SMEM_REQ);
    cudaFuncSetAttribute(mma_gemm_kernel<true>,
                         cudaFuncAttributeMaxDynamicSharedMemorySize, SMEM_REQ);

    // 1) W = A-B, B -> fp16
    prep_w_kernel<<<(G_DIM * H_DIM * H_DIM) / 256, 256>>>(A, B);
    // 2) x -> fp16 and S = sum_k x3 -> fp16 (single pass over x)
    prep_x_s_kernel<<<BSZ, H_DIM>>>(x);
    // 3) T = S @ B^T            [4096 x 2048]
    mma_gemm_kernel<false><<<dim3(N_COLS / BN, BSZ / BM), NTHREADS, SMEM_REQ>>>(
        Sh, Bh, nullptr, T);
    // 4) out = remap(X @ W^T + T)  [32768 x 2048]
    mma_gemm_kernel<true><<<dim3(N_COLS / BN, M_MAIN / BM), NTHREADS, SMEM_REQ>>>(
        Xh, Wh, T, out);
}